// round 9
// baseline (speedup 1.0000x reference)
#include <cuda_runtime.h>
#include <cuda_bf16.h>
#include <cstdint>

typedef unsigned int uint;

#define C_IN    64
#define INHW    224
#define C_OUT   128
#define OHW     222
#define NPIX    (OHW*OHW)          // 49284
#define NTAP    9
#define NCHUNK  (NTAP*2)           // 18 k32 half-chunks
#define TILE_N  128
#define NTILES  ((NPIX + TILE_N - 1)/TILE_N)   // 386

// x transposed to [h][w][ic] bf16, split hi/lo (6.4 MB each)
__device__ __align__(16) __nv_bfloat16 g_xhi[INHW*INHW*C_IN];
__device__ __align__(16) __nv_bfloat16 g_xlo[INHW*INHW*C_IN];
// w rearranged to [tap][oc][ic] bf16, split hi/lo (144 KB each)
__device__ __align__(16) __nv_bfloat16 g_whi[NTAP*C_OUT*C_IN];
__device__ __align__(16) __nv_bfloat16 g_wlo[NTAP*C_OUT*C_IN];

// ---------------- prep kernels ----------------
__global__ void prep_x_kernel(const float* __restrict__ x) {
    int i = blockIdx.x * 256 + threadIdx.x;      // INHW*INHW*8 threads
    if (i >= INHW*INHW*8) return;
    int hw = i >> 3;
    int g  = i & 7;                               // ic group of 8
    __align__(16) __nv_bfloat16 hi[8];
    __align__(16) __nv_bfloat16 lo[8];
    #pragma unroll
    for (int q = 0; q < 8; ++q) {
        float v = x[(size_t)(g*8 + q) * (INHW*INHW) + hw];
        __nv_bfloat16 h = __float2bfloat16(v);
        hi[q] = h;
        lo[q] = __float2bfloat16(v - __bfloat162float(h));
    }
    *(uint4*)&g_xhi[(size_t)hw*64 + g*8] = *(const uint4*)hi;
    *(uint4*)&g_xlo[(size_t)hw*64 + g*8] = *(const uint4*)lo;
}

__global__ void prep_w_kernel(const float* __restrict__ w) {
    int i = blockIdx.x * 256 + threadIdx.x;      // 9*128*64 = 73728
    if (i >= NTAP*C_OUT*C_IN) return;
    int ic = i & 63;
    int r  = i >> 6;
    int oc = r & 127;
    int t  = r >> 7;
    float v = w[(size_t)(oc*C_IN + ic)*NTAP + t];
    __nv_bfloat16 h = __float2bfloat16(v);
    g_whi[i] = h;
    g_wlo[i] = __float2bfloat16(v - __bfloat162float(h));
}

// ---------------- PTX helpers (all sm_80-era, compute_103-safe) ----------------
__device__ __forceinline__ uint smem_u32(const void* p) {
    uint a;
    asm("{ .reg .u64 t; cvta.to.shared.u64 t, %1; cvt.u32.u64 %0, t; }"
        : "=r"(a) : "l"(p));
    return a;
}
__device__ __forceinline__ void cpa16(uint d, const void* s) {
    asm volatile("cp.async.ca.shared.global [%0], [%1], 16;" :: "r"(d), "l"(s) : "memory");
}
__device__ __forceinline__ void cpa_commit() {
    asm volatile("cp.async.commit_group;" ::: "memory");
}
__device__ __forceinline__ void cpa_wait1() {
    asm volatile("cp.async.wait_group 1;" ::: "memory");
}
__device__ __forceinline__ void cpa_wait0() {
    asm volatile("cp.async.wait_group 0;" ::: "memory");
}
__device__ __forceinline__ void ldsm4(uint& r0, uint& r1, uint& r2, uint& r3, uint a) {
    asm volatile("ldmatrix.sync.aligned.m8n8.x4.shared.b16 {%0,%1,%2,%3}, [%4];"
                 : "=r"(r0), "=r"(r1), "=r"(r2), "=r"(r3) : "r"(a));
}
__device__ __forceinline__ void mma_bf16(float* c, const uint* a, uint b0, uint b1) {
    asm volatile("mma.sync.aligned.m16n8k16.row.col.f32.bf16.bf16.f32 "
                 "{%0,%1,%2,%3}, {%4,%5,%6,%7}, {%8,%9}, {%0,%1,%2,%3};"
                 : "+f"(c[0]), "+f"(c[1]), "+f"(c[2]), "+f"(c[3])
                 : "r"(a[0]), "r"(a[1]), "r"(a[2]), "r"(a[3]), "r"(b0), "r"(b1));
}

// ---------------- SMEM layout (single 64 KB tap buffer; k32 halves = ring slots) ----------------
#define SM_A_HI   0
#define SM_A_LO   16384
#define SM_B_HI   32768
#define SM_B_LO   49152
#define SMEM_SZ   65536

// ---------------- main kernel ----------------
__global__ __launch_bounds__(256, 2)
void conv_hmma_pipe_kernel(float* __restrict__ out)
{
    extern __shared__ char smem[];
    const uint sb  = smem_u32(smem);
    const int tid  = threadIdx.x;
    const int wid  = tid >> 5;
    const int lid  = tid & 31;
    const int wm   = wid & 1;          // m-half (64 rows)
    const int wn   = wid >> 1;         // n-quarter (32 cols)

    const size_t p0 = (size_t)blockIdx.x * TILE_N;

    // ---- staging assignment (tid<128: A row 'tid'; tid>=128: B row 'tid-128') ----
    const int srow  = tid & 127;
    const int rowsw = srow & 7;                 // swizzle key for this staged row
    const char* srcH;
    const char* srcL;
    if (tid < 128) {
        srcH = (const char*)g_whi + (size_t)srow * 128;
        srcL = (const char*)g_wlo + (size_t)srow * 128;
    } else {
        size_t p = p0 + srow; if (p >= NPIX) p = NPIX - 1;   // masked at store
        const int boh = (int)(p / OHW), bow = (int)(p - (size_t)boh * OHW);
        srcH = (const char*)g_xhi + ((size_t)boh * INHW + bow) * 128;
        srcL = (const char*)g_xlo + ((size_t)boh * INHW + bow) * 128;
    }
    const uint dH = sb + (tid < 128 ? SM_A_HI : SM_B_HI) + (uint)srow * 128;
    const uint dL = sb + (tid < 128 ? SM_A_LO : SM_B_LO) + (uint)srow * 128;
    const bool isA = (tid < 128);

    // ---- ldmatrix per-lane bases ----
    const int  rA = wm * 64 + (lid & 15);
    const int  sA = lid >> 4;
    const uint aHbase = sb + SM_A_HI + (uint)rA * 128;
    const uint aLbase = sb + SM_A_LO + (uint)rA * 128;
    const int  rB = wn * 32 + ((lid >> 4) << 3) + (lid & 7);
    const int  sB = (lid >> 3) & 1;
    const uint bHbase = sb + SM_B_HI + (uint)rB * 128;
    const uint bLbase = sb + SM_B_LO + (uint)rB * 128;
    const int  cA = rA & 7;
    const int  cB = rB & 7;

    float acc[64];
    #pragma unroll
    for (int i = 0; i < 64; ++i) acc[i] = 0.f;

    // ---- stage one k32 half-chunk ----
    // A k32 half = 2 k16 segments = granules 4h..4h+3 of each 128B row
    // (granule g of 16B pairs with k16 step k via g = 2k + s, s in {0,1}).
    auto stage = [&](int c) {
        const int t  = c >> 1;
        const int h  = c & 1;
        const int kr = t / 3, ks = t - kr * 3;
        const size_t off = isA ? (size_t)t * ((size_t)C_OUT * 128)
                               : (size_t)(kr * INHW + ks) * 128;
        #pragma unroll
        for (int jj = 0; jj < 4; ++jj) {
            const int  j  = 4 * h + jj;                 // granules 4h..4h+3
            const uint sw = (uint)((j ^ rowsw) << 4);
            cpa16(dH + sw, srcH + off + j * 16);
            cpa16(dL + sw, srcL + off + j * 16);
        }
    };

    // prologue
    stage(0);
    cpa_commit();

    #pragma unroll 1
    for (int c = 0; c < NCHUNK; ++c) {
        if (c + 1 < NCHUNK) {
            stage(c + 1);          // writes the OTHER k32 column-half (or next tap's
            cpa_commit();          //  first half, overwriting chunk c-1's granules,
            cpa_wait1();           //  whose reads finished behind the last barrier)
        } else {
            cpa_wait0();
        }
        __syncthreads();           // chunk c visible to all warps

        // ---- compute chunk c: k16-steps {2h, 2h+1}, 3 passes fused ----
        const int h = c & 1;
        #pragma unroll
        for (int kk = 0; kk < 2; ++kk) {
            const int k = 2 * h + kk;
            uint bhi[8], blo[8];
            #pragma unroll
            for (int q = 0; q < 2; ++q) {
                const uint segoff = (uint)(((2 * k + sB) ^ cB) << 4) + (uint)q * 2048;
                ldsm4(bhi[q*4+0], bhi[q*4+1], bhi[q*4+2], bhi[q*4+3], bHbase + segoff);
                ldsm4(blo[q*4+0], blo[q*4+1], blo[q*4+2], blo[q*4+3], bLbase + segoff);
            }
            #pragma unroll
            for (int i = 0; i < 4; ++i) {
                const uint segA = (uint)(((2 * k + sA) ^ cA) << 4) + (uint)i * 2048;
                uint ahi[4], alo[4];
                ldsm4(ahi[0], ahi[1], ahi[2], ahi[3], aHbase + segA);
                ldsm4(alo[0], alo[1], alo[2], alo[3], aLbase + segA);
                #pragma unroll
                for (int j = 0; j < 4; ++j) {
                    float* cacc = &acc[(i * 4 + j) * 4];
                    mma_bf16(cacc, ahi, bhi[j*2], bhi[j*2+1]);   // Whi*Xhi
                    mma_bf16(cacc, ahi, blo[j*2], blo[j*2+1]);   // Whi*Xlo
                    mma_bf16(cacc, alo, bhi[j*2], bhi[j*2+1]);   // Wlo*Xhi
                }
            }
        }
        __syncthreads();           // all reads of chunk c done before c+2 overwrites
    }

    // ---- epilogue ----
    const int ml = wm * 64 + (lid >> 2);
    const int nl = wn * 32 + (lid & 3) * 2;
    #pragma unroll
    for (int i = 0; i < 4; ++i) {
        #pragma unroll
        for (int j = 0; j < 4; ++j) {
            const float* c = &acc[(i * 4 + j) * 4];
            const int n = nl + j * 8;
            const size_t p = p0 + n;
            if (p < NPIX) {                       // NPIX%4==0 -> pair fully valid
                const int m0 = ml + i * 16;
                *(float2*)(out + (size_t)m0 * NPIX + p)       = make_float2(c[0], c[1]);
                *(float2*)(out + (size_t)(m0 + 8) * NPIX + p) = make_float2(c[2], c[3]);
            }
        }
    }
}

// ---------------- launch ----------------
extern "C" void kernel_launch(void* const* d_in, const int* in_sizes, int n_in,
                              void* d_out, int out_size)
{
    const float* x = (const float*)d_in[0];   // (64, 224, 224) f32
    const float* w = (const float*)d_in[1];   // (128, 64, 3, 3) f32
    float* out = (float*)d_out;               // (128, 222, 222) f32

    cudaFuncSetAttribute(conv_hmma_pipe_kernel,
                         cudaFuncAttributeMaxDynamicSharedMemorySize, SMEM_SZ);

    prep_x_kernel<<<(INHW*INHW*8 + 255) / 256, 256>>>(x);
    prep_w_kernel<<<(NTAP*C_OUT*C_IN + 255) / 256, 256>>>(w);
    conv_hmma_pipe_kernel<<<NTILES, 256, SMEM_SZ>>>(out);
}